// round 1
// baseline (speedup 1.0000x reference)
#include <cuda_runtime.h>

#define BB 2
#define SS 4096
#define DD 768
#define HH 12
#define HDD 64
#define PADW 68   // 64 + 4 pad: breaks stride-64 SMEM bank conflicts

// Scratch (device globals: no allocations allowed in kernel_launch)
__device__ float g_q[BB*SS*DD];
__device__ float g_k[BB*SS*DD];
__device__ float g_v[BB*SS*DD];
__device__ float g_ctx[BB*SS*DD];

// ---------------------------------------------------------------------------
// GEMM: C[M,N] = A[M,K] @ W[N,K]^T (+ bias). BM=128, BN=64, BK=16, 256 thr.
// Each thread computes an 8x4 micro-tile. A staged transposed (As[k][m]) so
// the inner loop reads float4s; per k-step: 3 LDS.128 feed 32 FFMA.
// Shapes here are exact multiples (M=8192, N=768, K=768) -> no bounds checks.
// ---------------------------------------------------------------------------
__global__ __launch_bounds__(256) void gemm_xwt(
    const float* __restrict__ A, const float* __restrict__ W,
    const float* __restrict__ bias, float* __restrict__ C,
    int M, int N, int K)
{
    __shared__ float As[16][128];
    __shared__ float Bs[16][64];

    const int tid = threadIdx.x;
    const int tx = tid & 15;        // 0..15 -> 4 cols each
    const int ty = tid >> 4;        // 0..15 -> 8 rows each
    const int bm = blockIdx.y * 128;
    const int bn = blockIdx.x * 64;

    const int ldRow = tid >> 2;           // 0..63
    const int ldCol = (tid & 3) << 2;     // 0,4,8,12

    const float* Ap0 = A + (size_t)(bm + ldRow) * K + ldCol;
    const float* Ap1 = Ap0 + (size_t)64 * K;
    const float* Wp  = W + (size_t)(bn + ldRow) * K + ldCol;

    float acc[8][4];
#pragma unroll
    for (int i = 0; i < 8; i++)
#pragma unroll
        for (int j = 0; j < 4; j++) acc[i][j] = 0.f;

    for (int k0 = 0; k0 < K; k0 += 16) {
        float4 a0 = *(const float4*)(Ap0 + k0);
        float4 a1 = *(const float4*)(Ap1 + k0);
        float4 w0 = *(const float4*)(Wp + k0);
        __syncthreads();                       // prev iter done reading smem
        As[ldCol+0][ldRow]    = a0.x;
        As[ldCol+1][ldRow]    = a0.y;
        As[ldCol+2][ldRow]    = a0.z;
        As[ldCol+3][ldRow]    = a0.w;
        As[ldCol+0][ldRow+64] = a1.x;
        As[ldCol+1][ldRow+64] = a1.y;
        As[ldCol+2][ldRow+64] = a1.z;
        As[ldCol+3][ldRow+64] = a1.w;
        Bs[ldCol+0][ldRow] = w0.x;
        Bs[ldCol+1][ldRow] = w0.y;
        Bs[ldCol+2][ldRow] = w0.z;
        Bs[ldCol+3][ldRow] = w0.w;
        __syncthreads();
#pragma unroll
        for (int kk = 0; kk < 16; kk++) {
            float4 av0 = *(const float4*)&As[kk][ty*8];
            float4 av1 = *(const float4*)&As[kk][ty*8+4];
            float4 bv  = *(const float4*)&Bs[kk][tx*4];
            float a[8] = {av0.x,av0.y,av0.z,av0.w,av1.x,av1.y,av1.z,av1.w};
            float b[4] = {bv.x,bv.y,bv.z,bv.w};
#pragma unroll
            for (int i = 0; i < 8; i++)
#pragma unroll
                for (int j = 0; j < 4; j++)
                    acc[i][j] += a[i] * b[j];
        }
    }

    float4 bias4 = make_float4(0.f, 0.f, 0.f, 0.f);
    if (bias) bias4 = *(const float4*)(bias + bn + tx*4);
#pragma unroll
    for (int i = 0; i < 8; i++) {
        float4 r;
        r.x = acc[i][0] + bias4.x;
        r.y = acc[i][1] + bias4.y;
        r.z = acc[i][2] + bias4.z;
        r.w = acc[i][3] + bias4.w;
        *(float4*)(C + (size_t)(bm + ty*8 + i) * N + bn + tx*4) = r;
    }
}

// ---------------------------------------------------------------------------
// Flash attention, causal. One CTA per (b, h, 128-query tile).
// BQ=128, BKT=64, HD=64. 256 threads, 16x16 grid: 8 q-rows x 4 cols each.
// Online softmax on scores/8; P staged through SMEM for the PV GEMM.
// ---------------------------------------------------------------------------
__global__ __launch_bounds__(256, 2) void attn_kernel()
{
    extern __shared__ float sm[];
    float* Qs = sm;                  // 128 x PADW
    float* Ks = Qs + 128*PADW;       // 64 x PADW
    float* Vs = Ks + 64*PADW;        // 64 x PADW
    float* Ps = Vs + 64*PADW;        // 128 x PADW

    const int tid = threadIdx.x;
    const int tx = tid & 15;
    const int ty = tid >> 4;
    const int bh = blockIdx.y;
    const int b  = bh / HH;
    const int h  = bh % HH;
    // heavy (late) q-tiles first: shrinks the causal load-imbalance tail
    const int qt = (gridDim.x - 1) - blockIdx.x;
    const int q0 = qt * 128;

    const float* Qg = g_q + ((size_t)b * SS) * DD + h * HDD;
    const float* Kg = g_k + ((size_t)b * SS) * DD + h * HDD;
    const float* Vg = g_v + ((size_t)b * SS) * DD + h * HDD;

    // load Q tile (coalesced: 16 threads x float4 cover a 64-float row)
    {
        const int c = tx * 4;
        for (int r = ty; r < 128; r += 16) {
            *(float4*)(Qs + r*PADW + c) =
                *(const float4*)(Qg + (size_t)(q0 + r) * DD + c);
        }
    }

    float m[8], l[8], o[8][4];
#pragma unroll
    for (int i = 0; i < 8; i++) {
        m[i] = -1e30f; l[i] = 0.f;
#pragma unroll
        for (int j = 0; j < 4; j++) o[i][j] = 0.f;
    }

    const int nkt = 2*qt + 2;                 // key tiles up to q0+127
    for (int kt = 0; kt < nkt; kt++) {
        const int k0 = kt * 64;
        __syncthreads();                      // prev PV done with Ks/Vs
        {
            const int c = tx * 4;
            for (int r = ty; r < 64; r += 16) {
                *(float4*)(Ks + r*PADW + c) =
                    *(const float4*)(Kg + (size_t)(k0 + r) * DD + c);
                *(float4*)(Vs + r*PADW + c) =
                    *(const float4*)(Vg + (size_t)(k0 + r) * DD + c);
            }
        }
        __syncthreads();

        // S = Q @ K^T for this tile
        float s[8][4];
#pragma unroll
        for (int i = 0; i < 8; i++)
#pragma unroll
            for (int j = 0; j < 4; j++) s[i][j] = 0.f;

        for (int d0 = 0; d0 < 64; d0 += 4) {
            float4 kv[4];
#pragma unroll
            for (int j = 0; j < 4; j++)
                kv[j] = *(const float4*)(Ks + (tx*4 + j)*PADW + d0);
#pragma unroll
            for (int i = 0; i < 8; i++) {
                float4 q = *(const float4*)(Qs + (ty*8 + i)*PADW + d0);
#pragma unroll
                for (int j = 0; j < 4; j++)
                    s[i][j] += q.x*kv[j].x + q.y*kv[j].y
                             + q.z*kv[j].z + q.w*kv[j].w;
            }
        }

        // scale by 1/sqrt(64) then causal mask (mask -> -1e30, exp -> 0)
        const bool need_mask = (k0 + 63 > q0);
#pragma unroll
        for (int i = 0; i < 8; i++)
#pragma unroll
            for (int j = 0; j < 4; j++) {
                float v = s[i][j] * 0.125f;
                if (need_mask && (k0 + tx*4 + j > q0 + ty*8 + i)) v = -1e30f;
                s[i][j] = v;
            }

        // online softmax; row owned by 16 lanes (xor<16 stays in-group)
#pragma unroll
        for (int i = 0; i < 8; i++) {
            float mt = fmaxf(fmaxf(s[i][0], s[i][1]), fmaxf(s[i][2], s[i][3]));
#pragma unroll
            for (int off = 8; off > 0; off >>= 1)
                mt = fmaxf(mt, __shfl_xor_sync(0xffffffffu, mt, off));
            const float mn = fmaxf(m[i], mt);
            const float alpha = __expf(m[i] - mn);
            float rs = 0.f;
#pragma unroll
            for (int j = 0; j < 4; j++) {
                float p = __expf(s[i][j] - mn);
                s[i][j] = p;
                rs += p;
            }
#pragma unroll
            for (int off = 8; off > 0; off >>= 1)
                rs += __shfl_xor_sync(0xffffffffu, rs, off);
            l[i] = l[i]*alpha + rs;
            m[i] = mn;
#pragma unroll
            for (int j = 0; j < 4; j++) o[i][j] *= alpha;
            *(float4*)(Ps + (ty*8 + i)*PADW + tx*4) =
                make_float4(s[i][0], s[i][1], s[i][2], s[i][3]);
        }
        __syncthreads();                      // Ps visible to everyone

        // O += P @ V
        for (int kk0 = 0; kk0 < 64; kk0 += 4) {
            float4 v4[4];
#pragma unroll
            for (int k = 0; k < 4; k++)
                v4[k] = *(const float4*)(Vs + (kk0 + k)*PADW + tx*4);
#pragma unroll
            for (int i = 0; i < 8; i++) {
                float4 p4 = *(const float4*)(Ps + (ty*8 + i)*PADW + kk0);
                o[i][0] += p4.x*v4[0].x + p4.y*v4[1].x + p4.z*v4[2].x + p4.w*v4[3].x;
                o[i][1] += p4.x*v4[0].y + p4.y*v4[1].y + p4.z*v4[2].y + p4.w*v4[3].y;
                o[i][2] += p4.x*v4[0].z + p4.y*v4[1].z + p4.z*v4[2].z + p4.w*v4[3].z;
                o[i][3] += p4.x*v4[0].w + p4.y*v4[1].w + p4.z*v4[2].w + p4.w*v4[3].w;
            }
        }
    }

    // normalize + write ctx in [b, s, h, hd] layout (natural for out-proj GEMM)
    float* Og = g_ctx + ((size_t)b * SS) * DD + h * HDD;
#pragma unroll
    for (int i = 0; i < 8; i++) {
        const float inv = 1.f / l[i];
        *(float4*)(Og + (size_t)(q0 + ty*8 + i) * DD + tx*4) =
            make_float4(o[i][0]*inv, o[i][1]*inv, o[i][2]*inv, o[i][3]*inv);
    }
}

// ---------------------------------------------------------------------------
extern "C" void kernel_launch(void* const* d_in, const int* in_sizes, int n_in,
                              void* d_out, int out_size)
{
    const float* x  = (const float*)d_in[0];
    const float* wq = (const float*)d_in[1];
    const float* wk = (const float*)d_in[2];
    const float* wv = (const float*)d_in[3];
    const float* wo = (const float*)d_in[4];
    const float* bo = (const float*)d_in[5];
    float* out = (float*)d_out;

    float *gq, *gk, *gv, *gctx;
    cudaGetSymbolAddress((void**)&gq,  g_q);
    cudaGetSymbolAddress((void**)&gk,  g_k);
    cudaGetSymbolAddress((void**)&gv,  g_v);
    cudaGetSymbolAddress((void**)&gctx, g_ctx);

    const int attn_smem = (2*128 + 2*64) * PADW * (int)sizeof(float); // 104448
    cudaFuncSetAttribute(attn_kernel,
                         cudaFuncAttributeMaxDynamicSharedMemorySize, attn_smem);

    dim3 gblock(256);
    dim3 ggrid(DD/64, (BB*SS)/128);   // (12, 64)

    gemm_xwt<<<ggrid, gblock>>>(x, wq, nullptr, gq, BB*SS, DD, DD);
    gemm_xwt<<<ggrid, gblock>>>(x, wk, nullptr, gk, BB*SS, DD, DD);
    gemm_xwt<<<ggrid, gblock>>>(x, wv, nullptr, gv, BB*SS, DD, DD);

    attn_kernel<<<dim3(SS/128, BB*HH), 256, attn_smem>>>();

    gemm_xwt<<<ggrid, gblock>>>(gctx, wo, bo, out, BB*SS, DD, DD);
}

// round 2
// speedup vs baseline: 2.4826x; 2.4826x over previous
#include <cuda_runtime.h>
#include <cstdint>

#define BB 2
#define SS 4096
#define DD 768
#define HH 12
#define HDD 64

// Scratch (device globals: no allocations allowed in kernel_launch)
__device__ float g_q[BB*SS*DD];
__device__ float g_k[BB*SS*DD];
__device__ float g_v[BB*SS*DD];
__device__ float g_ctx[BB*SS*DD];

// round fp32 -> tf32 (rna), result is fp32 bit-pattern with low mantissa zeroed
__device__ __forceinline__ uint32_t f2tf32(float x) {
    uint32_t u;
    asm("cvt.rna.tf32.f32 %0, %1;" : "=r"(u) : "f"(x));
    return u;
}

__device__ __forceinline__ void mma_tf32(
    float& d0, float& d1, float& d2, float& d3,
    uint32_t a0, uint32_t a1, uint32_t a2, uint32_t a3,
    uint32_t b0, uint32_t b1)
{
    asm volatile(
        "mma.sync.aligned.m16n8k8.row.col.f32.tf32.tf32.f32 "
        "{%0,%1,%2,%3}, {%4,%5,%6,%7}, {%8,%9}, {%0,%1,%2,%3};\n"
        : "+f"(d0), "+f"(d1), "+f"(d2), "+f"(d3)
        : "r"(a0), "r"(a1), "r"(a2), "r"(a3), "r"(b0), "r"(b1));
}

// k-pair permutation: logical k and k+4 (within each 8-group) stored adjacent,
// so (a0,a2)/(b0,b1) fragment pairs are one LDS.64.
__device__ __forceinline__ int pcol(int k) {
    return (k & ~7) + ((k & 3) << 1) + ((k >> 2) & 1);
}

// ---------------------------------------------------------------------------
// tf32 GEMM: C[M,N] = A[M,K] @ W[N,K]^T (+bias). CTA 128x128, BK=32,
// 8 warps (2x4) of 64x32. Row stride 40 floats => conflict-free LDS.64 frags.
// ---------------------------------------------------------------------------
#define GLD 40

__global__ __launch_bounds__(256) void gemm_tf32(
    const float* __restrict__ A, const float* __restrict__ W,
    const float* __restrict__ bias, float* __restrict__ C,
    int M, int N, int K, int round_out)
{
    __shared__ float As[128*GLD];
    __shared__ float Ws[128*GLD];

    const int tid  = threadIdx.x;
    const int lane = tid & 31;
    const int warp = tid >> 5;
    const int g = lane >> 2, tig = lane & 3;
    const int wm = warp & 1;          // 0..1 -> 64 rows each
    const int wn = warp >> 1;         // 0..3 -> 32 cols each
    const int bm = blockIdx.y * 128;
    const int bn = blockIdx.x * 128;

    float acc[4][4][4];
#pragma unroll
    for (int mi = 0; mi < 4; mi++)
#pragma unroll
        for (int ni = 0; ni < 4; ni++)
#pragma unroll
            for (int c = 0; c < 4; c++) acc[mi][ni][c] = 0.f;

    const int srow = tid >> 3;            // 0..31
    const int sc4  = (tid & 7) << 2;      // 0..28
    const int pb   = (sc4 & ~7) + ((sc4 >> 2) & 1);  // phys col base, step 2

    for (int k0 = 0; k0 < K; k0 += 32) {
        __syncthreads();
#pragma unroll
        for (int p = 0; p < 4; p++) {
            const int r = srow + 32*p;
            float4 a = *(const float4*)(A + (size_t)(bm + r)*K + k0 + sc4);
            As[r*GLD + pb+0] = __uint_as_float(f2tf32(a.x));
            As[r*GLD + pb+2] = __uint_as_float(f2tf32(a.y));
            As[r*GLD + pb+4] = __uint_as_float(f2tf32(a.z));
            As[r*GLD + pb+6] = __uint_as_float(f2tf32(a.w));
            float4 w = *(const float4*)(W + (size_t)(bn + r)*K + k0 + sc4);
            Ws[r*GLD + pb+0] = __uint_as_float(f2tf32(w.x));
            Ws[r*GLD + pb+2] = __uint_as_float(f2tf32(w.y));
            Ws[r*GLD + pb+4] = __uint_as_float(f2tf32(w.z));
            Ws[r*GLD + pb+6] = __uint_as_float(f2tf32(w.w));
        }
        __syncthreads();

#pragma unroll
        for (int kk = 0; kk < 4; kk++) {
            const int kc = kk*8 + 2*tig;   // physical col of (tig, tig+4) pair
            uint32_t b0[4], b1[4];
#pragma unroll
            for (int ni = 0; ni < 4; ni++) {
                float2 bf = *(const float2*)&Ws[(32*wn + 8*ni + g)*GLD + kc];
                b0[ni] = __float_as_uint(bf.x);
                b1[ni] = __float_as_uint(bf.y);
            }
#pragma unroll
            for (int mi = 0; mi < 4; mi++) {
                const int rb = 64*wm + 16*mi;
                float2 alo = *(const float2*)&As[(rb + g)*GLD + kc];
                float2 ahi = *(const float2*)&As[(rb + g + 8)*GLD + kc];
                const uint32_t a0 = __float_as_uint(alo.x);
                const uint32_t a1 = __float_as_uint(ahi.x);
                const uint32_t a2 = __float_as_uint(alo.y);
                const uint32_t a3 = __float_as_uint(ahi.y);
#pragma unroll
                for (int ni = 0; ni < 4; ni++)
                    mma_tf32(acc[mi][ni][0], acc[mi][ni][1],
                             acc[mi][ni][2], acc[mi][ni][3],
                             a0, a1, a2, a3, b0[ni], b1[ni]);
            }
        }
    }

#pragma unroll
    for (int ni = 0; ni < 4; ni++) {
        const int col = bn + 32*wn + 8*ni + 2*tig;
        float bx = 0.f, by = 0.f;
        if (bias) { bx = bias[col]; by = bias[col+1]; }
#pragma unroll
        for (int mi = 0; mi < 4; mi++) {
            const int r0 = bm + 64*wm + 16*mi + g;
            float v0 = acc[mi][ni][0] + bx, v1 = acc[mi][ni][1] + by;
            float v2 = acc[mi][ni][2] + bx, v3 = acc[mi][ni][3] + by;
            if (round_out) {   // q/k/v stored tf32-rounded: attention mma is lossless
                v0 = __uint_as_float(f2tf32(v0));
                v1 = __uint_as_float(f2tf32(v1));
                v2 = __uint_as_float(f2tf32(v2));
                v3 = __uint_as_float(f2tf32(v3));
            }
            *(float2*)(C + (size_t)r0*N + col)     = make_float2(v0, v1);
            *(float2*)(C + (size_t)(r0+8)*N + col) = make_float2(v2, v3);
        }
    }
}

// ---------------------------------------------------------------------------
// Flash attention on tf32 mma. One CTA = (b,h,128-q-tile), 4 warps, each warp
// owns a 32-row band (softmax warp-local). 64 keys per iteration.
// SMEM row stride 72 floats: conflict-free frag LDS.64 and V LDS.32.
// ---------------------------------------------------------------------------
#define ALD 72

__global__ __launch_bounds__(128) void attn_mma()
{
    extern __shared__ float smm[];
    float* Qs = smm;                 // 128 x ALD (k-pair permuted)
    float* Ks = Qs + 128*ALD;        // 64 x ALD  (k-pair permuted)
    float* Vs = Ks + 64*ALD;         // 64 x ALD  (direct: row=key, col=hd)
    float* Ps = Vs + 64*ALD;         // 128 x ALD (key-pair permuted)

    const int tid  = threadIdx.x;
    const int lane = tid & 31;
    const int warp = tid >> 5;
    const int g = lane >> 2, tig = lane & 3;
    const int bh = blockIdx.y;
    const int b  = bh / HH;
    const int h  = bh % HH;
    const int qt = (gridDim.x - 1) - blockIdx.x;   // heavy tiles first
    const int q0 = qt * 128;

    const float* Qg = g_q + ((size_t)b * SS) * DD + h * HDD;
    const float* Kg = g_k + ((size_t)b * SS) * DD + h * HDD;
    const float* Vg = g_v + ((size_t)b * SS) * DD + h * HDD;

    // load Q: one row per thread, permuted columns
    {
        const float* src = Qg + (size_t)(q0 + tid) * DD;
        float* dst = Qs + tid * ALD;
#pragma unroll
        for (int c = 0; c < 64; c += 4) {
            float4 v = *(const float4*)(src + c);
            const int p = (c & ~7) + ((c >> 2) & 1);
            dst[p+0] = v.x; dst[p+2] = v.y; dst[p+4] = v.z; dst[p+6] = v.w;
        }
    }

    float s[2][8][4], o[2][8][4], mrow[2][2], lrow[2][2];
#pragma unroll
    for (int mi = 0; mi < 2; mi++) {
#pragma unroll
        for (int hi = 0; hi < 2; hi++) { mrow[mi][hi] = -1e30f; lrow[mi][hi] = 0.f; }
#pragma unroll
        for (int ni = 0; ni < 8; ni++)
#pragma unroll
            for (int c = 0; c < 4; c++) o[mi][ni][c] = 0.f;
    }

    const int nkt = 2*qt + 2;
    for (int kt = 0; kt < nkt; kt++) {
        const int k0 = kt * 64;
        __syncthreads();                 // prev iter done with Ks/Vs
        {   // stage K (permuted) + V (direct): 2 threads per row
            const int r  = tid >> 1;
            const int ch = (tid & 1) * 32;
            const float* ksrc = Kg + (size_t)(k0 + r) * DD + ch;
            const float* vsrc = Vg + (size_t)(k0 + r) * DD + ch;
            float* kdst = Ks + r * ALD;
            float* vdst = Vs + r * ALD + ch;
#pragma unroll
            for (int c = 0; c < 32; c += 4) {
                float4 kv = *(const float4*)(ksrc + c);
                const int cc = ch + c;
                const int p = (cc & ~7) + ((cc >> 2) & 1);
                kdst[p+0] = kv.x; kdst[p+2] = kv.y; kdst[p+4] = kv.z; kdst[p+6] = kv.w;
                *(float4*)(vdst + c) = *(const float4*)(vsrc + c);
            }
        }
        __syncthreads();

        // ---- S = Q @ K^T (128x64) ----
#pragma unroll
        for (int mi = 0; mi < 2; mi++)
#pragma unroll
            for (int ni = 0; ni < 8; ni++)
#pragma unroll
                for (int c = 0; c < 4; c++) s[mi][ni][c] = 0.f;

#pragma unroll
        for (int kk = 0; kk < 8; kk++) {
            const int kc = kk*8 + 2*tig;
            uint32_t b0[8], b1[8];
#pragma unroll
            for (int ni = 0; ni < 8; ni++) {
                float2 bf = *(const float2*)&Ks[(8*ni + g)*ALD + kc];
                b0[ni] = __float_as_uint(bf.x);
                b1[ni] = __float_as_uint(bf.y);
            }
#pragma unroll
            for (int mi = 0; mi < 2; mi++) {
                const int rb = 32*warp + 16*mi;
                float2 alo = *(const float2*)&Qs[(rb + g)*ALD + kc];
                float2 ahi = *(const float2*)&Qs[(rb + g + 8)*ALD + kc];
                const uint32_t a0 = __float_as_uint(alo.x);
                const uint32_t a1 = __float_as_uint(ahi.x);
                const uint32_t a2 = __float_as_uint(alo.y);
                const uint32_t a3 = __float_as_uint(ahi.y);
#pragma unroll
                for (int ni = 0; ni < 8; ni++)
                    mma_tf32(s[mi][ni][0], s[mi][ni][1], s[mi][ni][2], s[mi][ni][3],
                             a0, a1, a2, a3, b0[ni], b1[ni]);
            }
        }

        // ---- online softmax (rows warp-local; 4-lane groups share a row) ----
        const bool need_mask = (k0 + 63 > q0);
#pragma unroll
        for (int mi = 0; mi < 2; mi++) {
#pragma unroll
            for (int hi = 0; hi < 2; hi++) {
                const int row = q0 + 32*warp + 16*mi + g + 8*hi;
                float mx = -1e30f;
#pragma unroll
                for (int ni = 0; ni < 8; ni++) {
#pragma unroll
                    for (int cc = 0; cc < 2; cc++) {
                        float v = s[mi][ni][2*hi+cc] * 0.125f;
                        if (need_mask && (k0 + 8*ni + 2*tig + cc > row)) v = -1e30f;
                        s[mi][ni][2*hi+cc] = v;
                        mx = fmaxf(mx, v);
                    }
                }
                mx = fmaxf(mx, __shfl_xor_sync(0xffffffffu, mx, 1));
                mx = fmaxf(mx, __shfl_xor_sync(0xffffffffu, mx, 2));
                const float mn = fmaxf(mrow[mi][hi], mx);
                const float alpha = __expf(mrow[mi][hi] - mn);
                mrow[mi][hi] = mn;
                float rs = 0.f;
#pragma unroll
                for (int ni = 0; ni < 8; ni++) {
#pragma unroll
                    for (int cc = 0; cc < 2; cc++) {
                        const float p = __expf(s[mi][ni][2*hi+cc] - mn);
                        s[mi][ni][2*hi+cc] = p;
                        rs += p;
                    }
                }
                rs += __shfl_xor_sync(0xffffffffu, rs, 1);
                rs += __shfl_xor_sync(0xffffffffu, rs, 2);
                lrow[mi][hi] = lrow[mi][hi]*alpha + rs;
#pragma unroll
                for (int ni = 0; ni < 8; ni++) {
                    o[mi][ni][2*hi+0] *= alpha;
                    o[mi][ni][2*hi+1] *= alpha;
                }
            }
        }

        // ---- P -> SMEM (warp-private band, tf32-rounded, key-pair permuted) ----
        __syncwarp();
#pragma unroll
        for (int mi = 0; mi < 2; mi++) {
#pragma unroll
            for (int hi = 0; hi < 2; hi++) {
                const int r = 32*warp + 16*mi + g + 8*hi;
#pragma unroll
                for (int ni = 0; ni < 8; ni++) {
#pragma unroll
                    for (int cc = 0; cc < 2; cc++) {
                        const int kcolv = 8*ni + 2*tig + cc;
                        Ps[r*ALD + pcol(kcolv)] =
                            __uint_as_float(f2tf32(s[mi][ni][2*hi+cc]));
                    }
                }
            }
        }
        __syncwarp();

        // ---- O += P @ V ----
#pragma unroll
        for (int kk = 0; kk < 8; kk++) {
            const int kc  = kk*8 + 2*tig;
            const int kr0 = kk*8 + tig;
            const int kr1 = kr0 + 4;
            uint32_t b0[8], b1[8];
#pragma unroll
            for (int ni = 0; ni < 8; ni++) {
                b0[ni] = __float_as_uint(Vs[kr0*ALD + 8*ni + g]);
                b1[ni] = __float_as_uint(Vs[kr1*ALD + 8*ni + g]);
            }
#pragma unroll
            for (int mi = 0; mi < 2; mi++) {
                const int rb = 32*warp + 16*mi;
                float2 alo = *(const float2*)&Ps[(rb + g)*ALD + kc];
                float2 ahi = *(const float2*)&Ps[(rb + g + 8)*ALD + kc];
                const uint32_t a0 = __float_as_uint(alo.x);
                const uint32_t a1 = __float_as_uint(ahi.x);
                const uint32_t a2 = __float_as_uint(alo.y);
                const uint32_t a3 = __float_as_uint(ahi.y);
#pragma unroll
                for (int ni = 0; ni < 8; ni++)
                    mma_tf32(o[mi][ni][0], o[mi][ni][1], o[mi][ni][2], o[mi][ni][3],
                             a0, a1, a2, a3, b0[ni], b1[ni]);
            }
        }
    }

    // ---- normalize + write ctx [b, s, h, hd] ----
#pragma unroll
    for (int mi = 0; mi < 2; mi++) {
#pragma unroll
        for (int hi = 0; hi < 2; hi++) {
            const float inv = 1.f / lrow[mi][hi];
            const int row = q0 + 32*warp + 16*mi + g + 8*hi;
            float* dst = g_ctx + ((size_t)b * SS + row) * DD + h * HDD;
#pragma unroll
            for (int ni = 0; ni < 8; ni++) {
                *(float2*)(dst + 8*ni + 2*tig) =
                    make_float2(o[mi][ni][2*hi+0]*inv, o[mi][ni][2*hi+1]*inv);
            }
        }
    }
}

// ---------------------------------------------------------------------------
extern "C" void kernel_launch(void* const* d_in, const int* in_sizes, int n_in,
                              void* d_out, int out_size)
{
    const float* x  = (const float*)d_in[0];
    const float* wq = (const float*)d_in[1];
    const float* wk = (const float*)d_in[2];
    const float* wv = (const float*)d_in[3];
    const float* wo = (const float*)d_in[4];
    const float* bo = (const float*)d_in[5];
    float* out = (float*)d_out;

    float *gq, *gk, *gv, *gctx;
    cudaGetSymbolAddress((void**)&gq,   g_q);
    cudaGetSymbolAddress((void**)&gk,   g_k);
    cudaGetSymbolAddress((void**)&gv,   g_v);
    cudaGetSymbolAddress((void**)&gctx, g_ctx);

    const int attn_smem = 384 * ALD * (int)sizeof(float);   // 110592 B
    cudaFuncSetAttribute(attn_mma,
                         cudaFuncAttributeMaxDynamicSharedMemorySize, attn_smem);

    dim3 gblock(256);
    dim3 ggrid(DD/128, (BB*SS)/128);    // (6, 64)

    gemm_tf32<<<ggrid, gblock>>>(x, wq, nullptr, gq, BB*SS, DD, DD, 1);
    gemm_tf32<<<ggrid, gblock>>>(x, wk, nullptr, gk, BB*SS, DD, DD, 1);
    gemm_tf32<<<ggrid, gblock>>>(x, wv, nullptr, gv, BB*SS, DD, DD, 1);

    attn_mma<<<dim3(SS/128, BB*HH), 128, attn_smem>>>();

    gemm_tf32<<<ggrid, gblock>>>(gctx, wo, bo, out, BB*SS, DD, DD, 0);
}

// round 3
// speedup vs baseline: 4.3920x; 1.7691x over previous
#include <cuda_runtime.h>
#include <cstdint>

#define BB 2
#define SS 4096
#define DD 768
#define HH 12
#define HDD 64

// Scratch (device globals: no allocations allowed in kernel_launch)
__device__ float g_q[BB*SS*DD];
__device__ float g_k[BB*SS*DD];
__device__ float g_v[BB*SS*DD];
__device__ float g_ctx[BB*SS*DD];
__device__ float g_xr[BB*SS*DD];   // tf32-rounded x
__device__ float g_wr[4*DD*DD];    // tf32-rounded wq,wk,wv,wo

__device__ __forceinline__ uint32_t f2tf32(float x) {
    uint32_t u;
    asm("cvt.rna.tf32.f32 %0, %1;" : "=r"(u) : "f"(x));
    return u;
}
__device__ __forceinline__ float rtf(float x) { return __uint_as_float(f2tf32(x)); }

__device__ __forceinline__ void mma_tf32(
    float& d0, float& d1, float& d2, float& d3,
    uint32_t a0, uint32_t a1, uint32_t a2, uint32_t a3,
    uint32_t b0, uint32_t b1)
{
    asm volatile(
        "mma.sync.aligned.m16n8k8.row.col.f32.tf32.tf32.f32 "
        "{%0,%1,%2,%3}, {%4,%5,%6,%7}, {%8,%9}, {%0,%1,%2,%3};\n"
        : "+f"(d0), "+f"(d1), "+f"(d2), "+f"(d3)
        : "r"(a0), "r"(a1), "r"(a2), "r"(a3), "r"(b0), "r"(b1));
}

__device__ __forceinline__ void cpa16(void* dst, const void* src) {
    uint32_t d = (uint32_t)__cvta_generic_to_shared(dst);
    asm volatile("cp.async.ca.shared.global [%0], [%1], 16;\n" :: "r"(d), "l"(src));
}
#define CP_COMMIT asm volatile("cp.async.commit_group;\n" ::: "memory")
#define CP_WAIT0  asm volatile("cp.async.wait_group 0;\n" ::: "memory")

// ---------------------------------------------------------------------------
// elementwise tf32 rounding (x and weights, once per launch)
// ---------------------------------------------------------------------------
__global__ void round_tf32(const float4* __restrict__ src,
                           float4* __restrict__ dst, int n4)
{
    int i = blockIdx.x * blockDim.x + threadIdx.x;
    if (i < n4) {
        float4 v = src[i];
        dst[i] = make_float4(rtf(v.x), rtf(v.y), rtf(v.z), rtf(v.w));
    }
}

// ---------------------------------------------------------------------------
// tf32 GEMM: C[M,N] = A[M,K] @ W[N,K]^T (+bias). CTA 128x128, BK=32,
// 8 warps (2x4) of 64x32. 2-stage cp.async pipeline. Inputs pre-rounded tf32.
// SMEM row stride 36 (mod 32 = 4): scalar frag LDS.32 banks = 4g+tig, clean.
// ---------------------------------------------------------------------------
#define GLD 36
#define GSTG (128*GLD)

__global__ __launch_bounds__(256) void gemm_tf32(
    const float* __restrict__ A, const float* __restrict__ W,
    const float* __restrict__ bias, float* __restrict__ C,
    int M, int N, int K, int round_out)
{
    extern __shared__ float gsm[];
    float* As = gsm;             // 2 stages x 128 x GLD
    float* Ws = gsm + 2*GSTG;

    const int tid  = threadIdx.x;
    const int lane = tid & 31;
    const int warp = tid >> 5;
    const int g = lane >> 2, tig = lane & 3;
    const int wm = warp & 1;
    const int wn = warp >> 1;
    const int bm = blockIdx.y * 128;
    const int bn = blockIdx.x * 128;

    float acc[4][4][4];
#pragma unroll
    for (int mi = 0; mi < 4; mi++)
#pragma unroll
        for (int ni = 0; ni < 4; ni++)
#pragma unroll
            for (int c = 0; c < 4; c++) acc[mi][ni][c] = 0.f;

    const int nk = K / 32;

    // stage issue: 128 rows x 8 16B-chunks each for A and W; 4 per thread
    {
#pragma unroll
        for (int i = 0; i < 4; i++) {
            const int id = tid + 256*i;
            const int r = id >> 3;
            const int c = (id & 7) << 2;
            cpa16(&As[r*GLD + c], A + (size_t)(bm + r)*K + c);
            cpa16(&Ws[r*GLD + c], W + (size_t)(bn + r)*K + c);
        }
        CP_COMMIT;
    }

    for (int it = 0; it < nk; it++) {
        CP_WAIT0;
        __syncthreads();
        const int s = it & 1;
        if (it + 1 < nk) {
            const int k1 = (it + 1) * 32;
            float* Ad = As + (s^1)*GSTG;
            float* Wd = Ws + (s^1)*GSTG;
#pragma unroll
            for (int i = 0; i < 4; i++) {
                const int id = tid + 256*i;
                const int r = id >> 3;
                const int c = (id & 7) << 2;
                cpa16(&Ad[r*GLD + c], A + (size_t)(bm + r)*K + k1 + c);
                cpa16(&Wd[r*GLD + c], W + (size_t)(bn + r)*K + k1 + c);
            }
            CP_COMMIT;
        }
        const float* Ab = As + s*GSTG;
        const float* Wb = Ws + s*GSTG;
#pragma unroll
        for (int kk = 0; kk < 4; kk++) {
            uint32_t b0[4], b1[4];
#pragma unroll
            for (int ni = 0; ni < 4; ni++) {
                const float* wp = Wb + (32*wn + 8*ni + g)*GLD + 8*kk + tig;
                b0[ni] = __float_as_uint(wp[0]);
                b1[ni] = __float_as_uint(wp[4]);
            }
#pragma unroll
            for (int mi = 0; mi < 4; mi++) {
                const int rb = 64*wm + 16*mi;
                const float* ap0 = Ab + (rb + g)*GLD + 8*kk + tig;
                const float* ap1 = Ab + (rb + g + 8)*GLD + 8*kk + tig;
                const uint32_t a0 = __float_as_uint(ap0[0]);
                const uint32_t a1 = __float_as_uint(ap1[0]);
                const uint32_t a2 = __float_as_uint(ap0[4]);
                const uint32_t a3 = __float_as_uint(ap1[4]);
#pragma unroll
                for (int ni = 0; ni < 4; ni++)
                    mma_tf32(acc[mi][ni][0], acc[mi][ni][1],
                             acc[mi][ni][2], acc[mi][ni][3],
                             a0, a1, a2, a3, b0[ni], b1[ni]);
            }
        }
    }

#pragma unroll
    for (int ni = 0; ni < 4; ni++) {
        const int col = bn + 32*wn + 8*ni + 2*tig;
        float bx = 0.f, by = 0.f;
        if (bias) { bx = bias[col]; by = bias[col+1]; }
#pragma unroll
        for (int mi = 0; mi < 4; mi++) {
            const int r0 = bm + 64*wm + 16*mi + g;
            float v0 = acc[mi][ni][0] + bx, v1 = acc[mi][ni][1] + by;
            float v2 = acc[mi][ni][2] + bx, v3 = acc[mi][ni][3] + by;
            if (round_out) {   // q/k/v stored tf32-rounded: attn mma stays exact
                v0 = rtf(v0); v1 = rtf(v1); v2 = rtf(v2); v3 = rtf(v3);
            }
            *(float2*)(C + (size_t)r0*N + col)     = make_float2(v0, v1);
            *(float2*)(C + (size_t)(r0+8)*N + col) = make_float2(v2, v3);
        }
    }
}

// ---------------------------------------------------------------------------
// Flash attention, tf32 mma, 4 warps (32-row bands, mi=2), BK=64.
// K/V double-buffered via cp.async; P stays in registers (shfl re-layout).
// Strides: Q/K 68 (banks 4g+tig), V 72 (banks 8tig+g) — conflict-free LDS.32.
// ---------------------------------------------------------------------------
#define KLD 68
#define VLD 72

__global__ __launch_bounds__(128) void attn_mma()
{
    extern __shared__ float smm[];
    float* Qs  = smm;                       // 128 x KLD
    float* Ksb = smm + 128*KLD;             // 2 x 64 x KLD
    float* Vsb = Ksb + 2*64*KLD;            // 2 x 64 x VLD

    const int tid  = threadIdx.x;
    const int lane = tid & 31;
    const int warp = tid >> 5;
    const int g = lane >> 2, tig = lane & 3;
    const int odd = tig & 1;
    const int bh = blockIdx.y;
    const int b  = bh / HH;
    const int h  = bh % HH;
    const int qt = (gridDim.x - 1) - blockIdx.x;   // heavy tiles first
    const int q0 = qt * 128;

    const float* Qg = g_q + ((size_t)b * SS) * DD + h * HDD;
    const float* Kg = g_k + ((size_t)b * SS) * DD + h * HDD;
    const float* Vg = g_v + ((size_t)b * SS) * DD + h * HDD;

    // prologue group: Q tile + K/V tile 0 (stage 0)
    {
#pragma unroll
        for (int i = 0; i < 16; i++) {            // Q: 128 rows x 16 chunks
            const int id = tid + 128*i;
            const int r = id >> 4;
            const int c = (id & 15) << 2;
            cpa16(&Qs[r*KLD + c], Qg + (size_t)(q0 + r)*DD + c);
        }
#pragma unroll
        for (int i = 0; i < 8; i++) {             // K,V: 64 rows x 16 chunks
            const int id = tid + 128*i;
            const int r = id >> 4;
            const int c = (id & 15) << 2;
            cpa16(&Ksb[r*KLD + c], Kg + (size_t)r*DD + c);
            cpa16(&Vsb[r*VLD + c], Vg + (size_t)r*DD + c);
        }
        CP_COMMIT;
    }

    float s[2][8][4], o[2][8][4], mrow[2][2], lrow[2][2];
#pragma unroll
    for (int mi = 0; mi < 2; mi++) {
#pragma unroll
        for (int hi = 0; hi < 2; hi++) { mrow[mi][hi] = -1e30f; lrow[mi][hi] = 0.f; }
#pragma unroll
        for (int ni = 0; ni < 8; ni++)
#pragma unroll
            for (int c = 0; c < 4; c++) o[mi][ni][c] = 0.f;
    }

    const int nkt = 2*qt + 2;
    for (int kt = 0; kt < nkt; kt++) {
        CP_WAIT0;
        __syncthreads();
        const int st = kt & 1;
        if (kt + 1 < nkt) {                      // prefetch next K/V tile
            const int k1 = (kt + 1) * 64;
            float* Kd = Ksb + (st^1)*64*KLD;
            float* Vd = Vsb + (st^1)*64*VLD;
#pragma unroll
            for (int i = 0; i < 8; i++) {
                const int id = tid + 128*i;
                const int r = id >> 4;
                const int c = (id & 15) << 2;
                cpa16(&Kd[r*KLD + c], Kg + (size_t)(k1 + r)*DD + c);
                cpa16(&Vd[r*VLD + c], Vg + (size_t)(k1 + r)*DD + c);
            }
            CP_COMMIT;
        }
        const float* Ks = Ksb + st*64*KLD;
        const float* Vs = Vsb + st*64*VLD;
        const int k0 = kt * 64;

        // ---- S = Q @ K^T ----
#pragma unroll
        for (int mi = 0; mi < 2; mi++)
#pragma unroll
            for (int ni = 0; ni < 8; ni++)
#pragma unroll
                for (int c = 0; c < 4; c++) s[mi][ni][c] = 0.f;

#pragma unroll
        for (int kk = 0; kk < 8; kk++) {
            uint32_t b0[8], b1[8];
#pragma unroll
            for (int ni = 0; ni < 8; ni++) {
                const float* kp = Ks + (8*ni + g)*KLD + 8*kk + tig;
                b0[ni] = __float_as_uint(kp[0]);
                b1[ni] = __float_as_uint(kp[4]);
            }
#pragma unroll
            for (int mi = 0; mi < 2; mi++) {
                const int rb = 32*warp + 16*mi;
                const float* qp0 = Qs + (rb + g)*KLD + 8*kk + tig;
                const float* qp1 = Qs + (rb + g + 8)*KLD + 8*kk + tig;
                const uint32_t a0 = __float_as_uint(qp0[0]);
                const uint32_t a1 = __float_as_uint(qp1[0]);
                const uint32_t a2 = __float_as_uint(qp0[4]);
                const uint32_t a3 = __float_as_uint(qp1[4]);
#pragma unroll
                for (int ni = 0; ni < 8; ni++)
                    mma_tf32(s[mi][ni][0], s[mi][ni][1], s[mi][ni][2], s[mi][ni][3],
                             a0, a1, a2, a3, b0[ni], b1[ni]);
            }
        }

        // ---- online softmax (rows warp-local; 4-lane groups share a row) ----
        const bool need_mask = (k0 + 63 > q0);
#pragma unroll
        for (int mi = 0; mi < 2; mi++) {
#pragma unroll
            for (int hi = 0; hi < 2; hi++) {
                const int row = q0 + 32*warp + 16*mi + g + 8*hi;
                float mx = -1e30f;
#pragma unroll
                for (int ni = 0; ni < 8; ni++) {
#pragma unroll
                    for (int cc = 0; cc < 2; cc++) {
                        float v = s[mi][ni][2*hi+cc] * 0.125f;
                        if (need_mask && (k0 + 8*ni + 2*tig + cc > row)) v = -1e30f;
                        s[mi][ni][2*hi+cc] = v;
                        mx = fmaxf(mx, v);
                    }
                }
                mx = fmaxf(mx, __shfl_xor_sync(0xffffffffu, mx, 1));
                mx = fmaxf(mx, __shfl_xor_sync(0xffffffffu, mx, 2));
                const float mn = fmaxf(mrow[mi][hi], mx);
                const float alpha = __expf(mrow[mi][hi] - mn);
                mrow[mi][hi] = mn;
                float rs = 0.f;
#pragma unroll
                for (int ni = 0; ni < 8; ni++) {
#pragma unroll
                    for (int cc = 0; cc < 2; cc++) {
                        const float p = __expf(s[mi][ni][2*hi+cc] - mn);
                        s[mi][ni][2*hi+cc] = p;
                        rs += p;
                    }
                }
                rs += __shfl_xor_sync(0xffffffffu, rs, 1);
                rs += __shfl_xor_sync(0xffffffffu, rs, 2);
                lrow[mi][hi] = lrow[mi][hi]*alpha + rs;
#pragma unroll
                for (int ni = 0; ni < 8; ni++) {
                    o[mi][ni][2*hi+0] *= alpha;
                    o[mi][ni][2*hi+1] *= alpha;
                }
            }
        }

        // ---- O += P @ V; P fragments built in-register via shfl ----
        // S-output lane layout: row g cols (2tig,2tig+1). PV A-frag needs row g
        // cols (tig, tig+4): source lanes base+(tig>>1) and base+(tig>>1)+2,
        // register selected by tig&1.
#pragma unroll
        for (int kk = 0; kk < 8; kk++) {
            uint32_t b0[8], b1[8];
#pragma unroll
            for (int ni = 0; ni < 8; ni++) {
                b0[ni] = __float_as_uint(Vs[(8*kk + tig)*VLD + 8*ni + g]);
                b1[ni] = __float_as_uint(Vs[(8*kk + tig + 4)*VLD + 8*ni + g]);
            }
            const int srcA = (lane & ~3) | (tig >> 1);
            const int srcB = srcA + 2;
#pragma unroll
            for (int mi = 0; mi < 2; mi++) {
                const float v0 = __shfl_sync(0xffffffffu, s[mi][kk][0], srcA);
                const float v1 = __shfl_sync(0xffffffffu, s[mi][kk][1], srcA);
                const float v2 = __shfl_sync(0xffffffffu, s[mi][kk][2], srcA);
                const float v3 = __shfl_sync(0xffffffffu, s[mi][kk][3], srcA);
                const float w0 = __shfl_sync(0xffffffffu, s[mi][kk][0], srcB);
                const float w1 = __shfl_sync(0xffffffffu, s[mi][kk][1], srcB);
                const float w2 = __shfl_sync(0xffffffffu, s[mi][kk][2], srcB);
                const float w3 = __shfl_sync(0xffffffffu, s[mi][kk][3], srcB);
                const uint32_t pa0 = f2tf32(odd ? v1 : v0);
                const uint32_t pa1 = f2tf32(odd ? v3 : v2);
                const uint32_t pa2 = f2tf32(odd ? w1 : w0);
                const uint32_t pa3 = f2tf32(odd ? w3 : w2);
#pragma unroll
                for (int ni = 0; ni < 8; ni++)
                    mma_tf32(o[mi][ni][0], o[mi][ni][1], o[mi][ni][2], o[mi][ni][3],
                             pa0, pa1, pa2, pa3, b0[ni], b1[ni]);
            }
        }
    }

    // ---- normalize + write ctx [b, s, h, hd] (tf32-rounded for out-proj) ----
#pragma unroll
    for (int mi = 0; mi < 2; mi++) {
#pragma unroll
        for (int hi = 0; hi < 2; hi++) {
            const float inv = 1.f / lrow[mi][hi];
            const int row = q0 + 32*warp + 16*mi + g + 8*hi;
            float* dst = g_ctx + ((size_t)b * SS + row) * DD + h * HDD;
#pragma unroll
            for (int ni = 0; ni < 8; ni++) {
                *(float2*)(dst + 8*ni + 2*tig) =
                    make_float2(rtf(o[mi][ni][2*hi+0]*inv),
                                rtf(o[mi][ni][2*hi+1]*inv));
            }
        }
    }
}

// ---------------------------------------------------------------------------
extern "C" void kernel_launch(void* const* d_in, const int* in_sizes, int n_in,
                              void* d_out, int out_size)
{
    const float* x  = (const float*)d_in[0];
    const float* wq = (const float*)d_in[1];
    const float* wk = (const float*)d_in[2];
    const float* wv = (const float*)d_in[3];
    const float* wo = (const float*)d_in[4];
    const float* bo = (const float*)d_in[5];
    float* out = (float*)d_out;

    float *gq, *gk, *gv, *gctx, *gxr, *gwr;
    cudaGetSymbolAddress((void**)&gq,   g_q);
    cudaGetSymbolAddress((void**)&gk,   g_k);
    cudaGetSymbolAddress((void**)&gv,   g_v);
    cudaGetSymbolAddress((void**)&gctx, g_ctx);
    cudaGetSymbolAddress((void**)&gxr,  g_xr);
    cudaGetSymbolAddress((void**)&gwr,  g_wr);

    const int gemm_smem = 4 * GSTG * (int)sizeof(float);        // 73728
    cudaFuncSetAttribute(gemm_tf32,
                         cudaFuncAttributeMaxDynamicSharedMemorySize, gemm_smem);
    const int attn_smem = (128*KLD + 2*64*KLD + 2*64*VLD) * (int)sizeof(float); // 106496
    cudaFuncSetAttribute(attn_mma,
                         cudaFuncAttributeMaxDynamicSharedMemorySize, attn_smem);

    // pre-round inputs to tf32 (rna) so GEMM cp.async staging is exact
    const int nx4 = BB*SS*DD/4, nw4 = DD*DD/4;
    round_tf32<<<(nx4+255)/256, 256>>>((const float4*)x,  (float4*)gxr, nx4);
    round_tf32<<<(nw4+255)/256, 256>>>((const float4*)wq, (float4*)(gwr + 0*DD*DD), nw4);
    round_tf32<<<(nw4+255)/256, 256>>>((const float4*)wk, (float4*)(gwr + 1*DD*DD), nw4);
    round_tf32<<<(nw4+255)/256, 256>>>((const float4*)wv, (float4*)(gwr + 2*DD*DD), nw4);
    round_tf32<<<(nw4+255)/256, 256>>>((const float4*)wo, (float4*)(gwr + 3*DD*DD), nw4);

    dim3 gblock(256);
    dim3 ggrid(DD/128, (BB*SS)/128);    // (6, 64)

    gemm_tf32<<<ggrid, gblock, gemm_smem>>>(gxr, gwr + 0*DD*DD, nullptr, gq, BB*SS, DD, DD, 1);
    gemm_tf32<<<ggrid, gblock, gemm_smem>>>(gxr, gwr + 1*DD*DD, nullptr, gk, BB*SS, DD, DD, 1);
    gemm_tf32<<<ggrid, gblock, gemm_smem>>>(gxr, gwr + 2*DD*DD, nullptr, gv, BB*SS, DD, DD, 1);

    attn_mma<<<dim3(SS/128, BB*HH), 128, attn_smem>>>();

    gemm_tf32<<<ggrid, gblock, gemm_smem>>>(gctx, gwr + 3*DD*DD, bo, out, BB*SS, DD, DD, 0);
}